// round 1
// baseline (speedup 1.0000x reference)
#include <cuda_runtime.h>

#define EMAX   2048
#define NNODES 4096
#define LWALK  8
#define HIDDIM 128

// Scratch (no allocations allowed): adjacency linked lists + per-edge walk counts.
__device__ int g_head[NNODES];
__device__ int g_next[EMAX];
__device__ int g_diag[EMAX * LWALK];

// ---------------------------------------------------------------------------
// K1: reset per-node list heads
// ---------------------------------------------------------------------------
__global__ void k_init() {
    int v = blockIdx.x * blockDim.x + threadIdx.x;
    if (v < NNODES) g_head[v] = -1;
}

// ---------------------------------------------------------------------------
// K2: build in-edge lists: node v -> list of edges k with dst[k] == v
// ---------------------------------------------------------------------------
__global__ void k_build(const int* __restrict__ dst, int E) {
    int j = blockIdx.x * blockDim.x + threadIdx.x;
    if (j < E) g_next[j] = atomicExch(&g_head[dst[j]], j);
}

// ---------------------------------------------------------------------------
// K3: per-edge DFS counting non-backtracking closed walks of length 1..8.
// Successor of edge c: edges k with dst[k]==src[c] and src[k]!=dst[c]
// (exactly B[c,k]=1). diag(B^p)[i] = #walks of length p from i back to i.
// ---------------------------------------------------------------------------
__global__ void k_dfs(const int* __restrict__ src, const int* __restrict__ dst, int E) {
    int i = blockIdx.x * blockDim.x + threadIdx.x;
    if (i >= E) return;

    int counts[LWALK];
#pragma unroll
    for (int t = 0; t < LWALK; t++) counts[t] = 0;

    // stack entry packs (edge << 4) | depth; edge < 2048, depth <= 8
    const int STACK_CAP = 320;
    int stk[STACK_CAP];
    int sp = 0;
    stk[sp++] = (i << 4);  // depth 0 at edge i

    while (sp > 0) {
        int v = stk[--sp];
        int j = v >> 4;
        int t = v & 15;
        if (t > 0 && j == i) counts[t - 1]++;
        if (t < LWALK) {
            int sj = src[j];
            int dj = dst[j];
            for (int k = g_head[sj]; k >= 0; k = g_next[k]) {
                if (src[k] != dj) {
                    if (sp < STACK_CAP) stk[sp++] = (k << 4) | (t + 1);
                }
            }
        }
    }

#pragma unroll
    for (int t = 0; t < LWALK; t++) g_diag[i * LWALK + t] = counts[t];
}

// ---------------------------------------------------------------------------
// K4: per-graph segment sum of diag rows + MLP (8 -> 128 -> 1).
// One block per graph, 128 threads.
// ---------------------------------------------------------------------------
__global__ void k_mlp(const int* __restrict__ egraph,
                      const float* __restrict__ W1, const float* __restrict__ b1,
                      const float* __restrict__ W2, const float* __restrict__ b2,
                      float* __restrict__ out, int E) {
    int g   = blockIdx.x;
    int tid = threadIdx.x;  // 0..127

    __shared__ float red[HIDDIM * LWALK];
    __shared__ float sig[LWALK];
    __shared__ float pr[HIDDIM];

    float acc[LWALK];
#pragma unroll
    for (int t = 0; t < LWALK; t++) acc[t] = 0.0f;

    // edge_graph is sorted but a strided scan over E=2048 is trivially cheap (L2-hit)
    for (int i = tid; i < E; i += HIDDIM) {
        if (egraph[i] == g) {
#pragma unroll
            for (int t = 0; t < LWALK; t++) acc[t] += (float)g_diag[i * LWALK + t];
        }
    }
#pragma unroll
    for (int t = 0; t < LWALK; t++) red[tid * LWALK + t] = acc[t];
    __syncthreads();

    if (tid < LWALK) {
        float s = 0.0f;
        for (int x = 0; x < HIDDIM; x++) s += red[x * LWALK + tid];
        sig[tid] = s;
    }
    __syncthreads();

    // hidden unit per thread
    float s = b1[tid];
#pragma unroll
    for (int t = 0; t < LWALK; t++) s += sig[t] * W1[t * HIDDIM + tid];
    float h = fmaxf(s, 0.0f);
    pr[tid] = h * W2[tid];
    __syncthreads();

    for (int off = HIDDIM / 2; off > 0; off >>= 1) {
        if (tid < off) pr[tid] += pr[tid + off];
        __syncthreads();
    }
    if (tid == 0) out[g] = pr[0] + b2[0];
}

// ---------------------------------------------------------------------------
extern "C" void kernel_launch(void* const* d_in, const int* in_sizes, int n_in,
                              void* d_out, int out_size) {
    const int*   edge_index = (const int*)d_in[0];   // (2, E)
    const int*   edge_graph = (const int*)d_in[1];   // (E,)
    const float* W1         = (const float*)d_in[2]; // (L, HID)
    const float* b1         = (const float*)d_in[3]; // (HID,)
    const float* W2         = (const float*)d_in[4]; // (HID, 1)
    const float* b2         = (const float*)d_in[5]; // (1,)
    float*       out        = (float*)d_out;         // (G, 1)

    int E = in_sizes[0] / 2;
    const int* src = edge_index;
    const int* dst = edge_index + E;

    k_init<<<(NNODES + 255) / 256, 256>>>();
    k_build<<<(E + 127) / 128, 128>>>(dst, E);
    k_dfs<<<(E + 127) / 128, 128>>>(src, dst, E);
    k_mlp<<<out_size, HIDDIM>>>(edge_graph, W1, b1, W2, b2, out, E);
}

// round 2
// speedup vs baseline: 1.2411x; 1.2411x over previous
#include <cuda_runtime.h>

#define EMAX   2048
#define NNODES 4096
#define LWALK  8
#define HID    128
#define GPB    4      // graphs per block
#define TPB    128

// Per-block private world: full adjacency + this block's graph signatures.
struct Sh {
    int head[NNODES];     // 16 KB: node v -> first edge k with dst[k]==v
    int next[EMAX];       //  8 KB: linked list
    int src[EMAX];        //  8 KB
    int dst[EMAX];        //  8 KB
    int sig[GPB][LWALK];  // per-graph closed-walk counts
    int lo, hi;           // edge range of this block's graphs
};

__device__ __forceinline__ int lower_bound_i(const int* __restrict__ a, int n, int val) {
    int lo = 0, hi = n;
    while (lo < hi) {
        int m = (lo + hi) >> 1;
        if (a[m] < val) lo = m + 1; else hi = m;
    }
    return lo;
}

// Depth-unrolled DFS: walk<D> expands edge j at depth (LWALK-D).
// Successor k of edge j: dst[k]==src[j] && src[k]!=dst[j]  (B[j,k]==1).
// Returning to start edge i at depth (LWALK-D+1) -> closed walk of that length.
template <int D>
__device__ __forceinline__ void walk(int i, int j, const Sh& sh, int* cnt) {
    const int dj = sh.dst[j];
    for (int k = sh.head[sh.src[j]]; k >= 0; k = sh.next[k]) {
        if (sh.src[k] != dj) {
            if (k == i) cnt[LWALK - D]++;
            if constexpr (D > 1) walk<D - 1>(i, k, sh, cnt);
        }
    }
}

__global__ void __launch_bounds__(TPB, 1)
k_fused(const int* __restrict__ edge_index, const int* __restrict__ egraph,
        const float* __restrict__ W1, const float* __restrict__ b1,
        const float* __restrict__ W2, const float* __restrict__ b2,
        float* __restrict__ out, int E, int G) {
    __shared__ Sh sh;
    const int tid = threadIdx.x;
    const int g0  = blockIdx.x * GPB;
    const int* src = edge_index;
    const int* dst = edge_index + E;

    // ---- Phase A: stage inputs + init (all in smem) ----
    for (int v = tid; v < NNODES; v += TPB) sh.head[v] = -1;
    for (int i = tid; i < E; i += TPB) { sh.src[i] = src[i]; sh.dst[i] = dst[i]; }
    if (tid < GPB * LWALK) ((int*)sh.sig)[tid] = 0;
    if (tid == 0) sh.lo = lower_bound_i(egraph, E, g0);
    if (tid == 1) sh.hi = lower_bound_i(egraph, E, min(g0 + GPB, G));
    __syncthreads();

    // ---- Phase B: build in-edge linked lists (shared atomics) ----
    for (int i = tid; i < E; i += TPB)
        sh.next[i] = atomicExch(&sh.head[sh.dst[i]], i);
    __syncthreads();

    // ---- Phase C: DFS over this block's edges only ----
    for (int i = sh.lo + tid; i < sh.hi; i += TPB) {
        int cnt[LWALK];
#pragma unroll
        for (int t = 0; t < LWALK; t++) cnt[t] = 0;
        walk<LWALK>(i, i, sh, cnt);
        const int gl = egraph[i] - g0;
#pragma unroll
        for (int t = 0; t < LWALK; t++)
            if (cnt[t]) atomicAdd(&sh.sig[gl][t], cnt[t]);
    }
    __syncthreads();

    // ---- Phase D: MLP, one warp per graph ----
    const int w = tid >> 5, lane = tid & 31;
    const int g = g0 + w;
    if (w < GPB && g < G) {
        float sigf[LWALK];
#pragma unroll
        for (int t = 0; t < LWALK; t++) sigf[t] = (float)sh.sig[w][t];

        float p = 0.0f;
#pragma unroll
        for (int r = 0; r < HID / 32; r++) {
            const int u = lane + r * 32;
            float s = b1[u];
#pragma unroll
            for (int t = 0; t < LWALK; t++) s += sigf[t] * W1[t * HID + u];
            p += fmaxf(s, 0.0f) * W2[u];
        }
#pragma unroll
        for (int off = 16; off > 0; off >>= 1)
            p += __shfl_xor_sync(0xffffffffu, p, off);
        if (lane == 0) out[g] = p + b2[0];
    }
}

extern "C" void kernel_launch(void* const* d_in, const int* in_sizes, int n_in,
                              void* d_out, int out_size) {
    const int*   edge_index = (const int*)d_in[0];   // (2, E)
    const int*   edge_graph = (const int*)d_in[1];   // (E,)
    const float* W1         = (const float*)d_in[2]; // (L, HID)
    const float* b1         = (const float*)d_in[3]; // (HID,)
    const float* W2         = (const float*)d_in[4]; // (HID, 1)
    const float* b2         = (const float*)d_in[5]; // (1,)
    float*       out        = (float*)d_out;         // (G,)

    const int E = in_sizes[0] / 2;
    const int G = out_size;
    const int nblocks = (G + GPB - 1) / GPB;

    k_fused<<<nblocks, TPB>>>(edge_index, edge_graph, W1, b1, W2, b2, out, E, G);
}

// round 3
// speedup vs baseline: 1.6642x; 1.3409x over previous
#include <cuda_runtime.h>

#define EMAX   2048
#define NNODES 4096
#define LWALK  8
#define HID    128
#define GPB    4      // graphs per block
#define TPB    128
#define STKCAP 96     // >= LWALK * max_indegree; Poisson(0.5) max deg ~6-7

// Per-block private world: full adjacency + this block's graph signatures.
struct Sh {
    int  head[NNODES];     // 16 KB: node v -> first edge k with dst[k]==v
    int  next[EMAX];       //  8 KB: intrusive list
    int2 sd[EMAX];         // 16 KB: (src, dst) per edge, one LDS.64
    int  sig[GPB][LWALK];
    int  lo, hi;           // edge range of this block's graphs
};

__device__ __forceinline__ int lower_bound_i(const int* __restrict__ a, int n, int val) {
    int lo = 0, hi = n;
    while (lo < hi) {
        int m = (lo + hi) >> 1;
        if (a[m] < val) lo = m + 1; else hi = m;
    }
    return lo;
}

__global__ void __launch_bounds__(TPB, 1)
k_fused(const int* __restrict__ edge_index, const int* __restrict__ egraph,
        const float* __restrict__ W1, const float* __restrict__ b1,
        const float* __restrict__ W2, const float* __restrict__ b2,
        float* __restrict__ out, int E, int G) {
    __shared__ Sh sh;
    const int tid = threadIdx.x;
    const int g0  = blockIdx.x * GPB;
    const int* src = edge_index;
    const int* dst = edge_index + E;

    // ---- Phase A: stage inputs + init (all in smem) ----
    for (int v = tid; v < NNODES; v += TPB) sh.head[v] = -1;
    for (int i = tid; i < E; i += TPB) sh.sd[i] = make_int2(src[i], dst[i]);
    if (tid < GPB * LWALK) ((int*)sh.sig)[tid] = 0;
    if (tid == 0) sh.lo = lower_bound_i(egraph, E, g0);
    if (tid == 1) sh.hi = lower_bound_i(egraph, E, min(g0 + GPB, G));
    __syncthreads();

    // ---- Phase B: build in-edge lists: node v -> edges k with dst[k]==v ----
    for (int i = tid; i < E; i += TPB)
        sh.next[i] = atomicExch(&sh.head[sh.sd[i].y], i);
    __syncthreads();

    // ---- Phase C: flat iterative DFS per edge (no nested-loop divergence) ----
    // Successor k of edge j: dst[k]==src[j] && src[k]!=dst[j]  (B[j,k]==1).
    // Closed walk of length t back at start edge i -> cnt[t-1]++.
    for (int i = sh.lo + tid; i < sh.hi; i += TPB) {
        int cnt[LWALK];
#pragma unroll
        for (int t = 0; t < LWALK; t++) cnt[t] = 0;

        int stk[STKCAP];
        int sp = 0;
        stk[sp++] = (i << 4);  // (edge << 4) | depth

        while (sp > 0) {
            const int v = stk[--sp];
            const int j = v >> 4;
            const int t = v & 15;
            const int2 sdj = sh.sd[j];
            const int tn = t + 1;
            for (int k = sh.head[sdj.x]; k >= 0; k = sh.next[k]) {
                if (sh.sd[k].x != sdj.y) {          // non-backtracking
                    if (k == i) cnt[tn - 1]++;       // closed walk length tn
                    if (tn < LWALK && sp < STKCAP) stk[sp++] = (k << 4) | tn;
                }
            }
        }

        const int gl = egraph[i] - g0;
#pragma unroll
        for (int t = 0; t < LWALK; t++)
            if (cnt[t]) atomicAdd(&sh.sig[gl][t], cnt[t]);
    }
    __syncthreads();

    // ---- Phase D: MLP (8 -> 128 -> 1), one warp per graph ----
    const int w = tid >> 5, lane = tid & 31;
    const int g = g0 + w;
    if (w < GPB && g < G) {
        float sigf[LWALK];
#pragma unroll
        for (int t = 0; t < LWALK; t++) sigf[t] = (float)sh.sig[w][t];

        float p = 0.0f;
#pragma unroll
        for (int r = 0; r < HID / 32; r++) {
            const int u = lane + r * 32;
            float s = b1[u];
#pragma unroll
            for (int t = 0; t < LWALK; t++) s += sigf[t] * W1[t * HID + u];
            p += fmaxf(s, 0.0f) * W2[u];
        }
#pragma unroll
        for (int off = 16; off > 0; off >>= 1)
            p += __shfl_xor_sync(0xffffffffu, p, off);
        if (lane == 0) out[g] = p + b2[0];
    }
}

extern "C" void kernel_launch(void* const* d_in, const int* in_sizes, int n_in,
                              void* d_out, int out_size) {
    const int*   edge_index = (const int*)d_in[0];   // (2, E)
    const int*   edge_graph = (const int*)d_in[1];   // (E,)
    const float* W1         = (const float*)d_in[2]; // (L, HID)
    const float* b1         = (const float*)d_in[3]; // (HID,)
    const float* W2         = (const float*)d_in[4]; // (HID, 1)
    const float* b2         = (const float*)d_in[5]; // (1,)
    float*       out        = (float*)d_out;         // (G,)

    const int E = in_sizes[0] / 2;
    const int G = out_size;
    const int nblocks = (G + GPB - 1) / GPB;

    k_fused<<<nblocks, TPB>>>(edge_index, edge_graph, W1, b1, W2, b2, out, E, G);
}